// round 15
// baseline (speedup 1.0000x reference)
#include <cuda_runtime.h>
#include <cuda_bf16.h>
#include <cstdint>

#define N_NODES 100000
#define N_EDGES 1250000
#define F 64
#define K_DIM 128
#define CAP 96          // bucket capacity; P(Poisson(12.5) > 96) ~ 1e-40

// ---------------- device scratch ----------------
__device__ int g_count[N_NODES];              // in-degree (re-zeroed by gemm tail)
__device__ int g_esrc[(size_t)N_NODES * CAP]; // per-node src buckets (38.4 MB)

// W bf16-split fragments, mma m16n8k16 B layout:
// g_wsplit[(ks*8 + tl)*32 + lane] = {bh0, bh1, bl0, bl1} (each = bf16x2)
#define NFRAG (8 * 8 * 32)     // 2048
__device__ uint4 g_wsplit[NFRAG];

// split two fp32 into packed bf16x2 hi and lo (x = hi + lo, ~16 mantissa bits)
__device__ __forceinline__ void split_pair(float x0, float x1,
                                           unsigned& hi, unsigned& lo) {
    __nv_bfloat16 h0 = __float2bfloat16_rn(x0);
    __nv_bfloat16 h1 = __float2bfloat16_rn(x1);
    float r0 = x0 - __bfloat162float(h0);
    float r1 = x1 - __bfloat162float(h1);
    __nv_bfloat16 l0 = __float2bfloat16_rn(r0);
    __nv_bfloat16 l1 = __float2bfloat16_rn(r1);
    hi = (unsigned)__bfloat16_as_ushort(h0) | ((unsigned)__bfloat16_as_ushort(h1) << 16);
    lo = (unsigned)__bfloat16_as_ushort(l0) | ((unsigned)__bfloat16_as_ushort(l1) << 16);
}

__device__ __forceinline__ void mma_bf16(float d[4], const unsigned a[4],
                                         unsigned b0, unsigned b1) {
    asm volatile(
        "mma.sync.aligned.m16n8k16.row.col.f32.bf16.bf16.f32 "
        "{%0,%1,%2,%3}, {%4,%5,%6,%7}, {%8,%9}, {%0,%1,%2,%3};\n"
        : "+f"(d[0]), "+f"(d[1]), "+f"(d[2]), "+f"(d[3])
        : "r"(a[0]), "r"(a[1]), "r"(a[2]), "r"(a[3]), "r"(b0), "r"(b1));
}

// ---------------------------------------------------------------------------
// 1) single-pass bucket fill, 8 edges/thread (2 disjoint int4 quads: thread i
//    handles quads {i, i + QUADS/2}, i < QUADS/2) + W prep (last 8 blocks).
// ---------------------------------------------------------------------------
#define QUADS (N_EDGES / 4)                       // 312500 (even)
#define HALFQ (QUADS / 2)                         // 156250
#define FILL_BLOCKS ((HALFQ + 255) / 256)         // 611
#define PREP_BLOCKS ((NFRAG + 255) / 256)         // 8

__global__ __launch_bounds__(256) void fill_kernel(const int* __restrict__ src,
                                                   const int* __restrict__ dst,
                                                   const float* __restrict__ W) {
    if (blockIdx.x >= FILL_BLOCKS) {
        int idx = (blockIdx.x - FILL_BLOCKS) * 256 + threadIdx.x;
        if (idx < NFRAG) {
            int lane = idx & 31;
            int tl = (idx >> 5) & 7;
            int ks = idx >> 8;                 // 0..7, k-base = 16*ks
            int g = lane >> 2, t = lane & 3;
            int o = tl * 8 + g;
            const float* wr = W + o * K_DIM + ks * 16;
            unsigned bh0, bl0, bh1, bl1;
            split_pair(wr[2 * t],     wr[2 * t + 1], bh0, bl0);
            split_pair(wr[2 * t + 8], wr[2 * t + 9], bh1, bl1);
            g_wsplit[idx] = make_uint4(bh0, bh1, bl0, bl1);
        }
        return;
    }
    int i = blockIdx.x * blockDim.x + threadIdx.x;
    if (i >= HALFQ) return;                   // FIX: disjoint halves only
#pragma unroll
    for (int r = 0; r < 2; r++) {
        int ii = i + r * HALFQ;               // covers [0,QUADS) exactly once
        int4 s4 = ((const int4*)src)[ii];
        int4 d4 = ((const int4*)dst)[ii];
#pragma unroll
        for (int j = 0; j < 4; j++) {
            int d = (j == 0) ? d4.x : (j == 1) ? d4.y : (j == 2) ? d4.z : d4.w;
            int s = (j == 0) ? s4.x : (j == 1) ? s4.y : (j == 2) ? s4.z : s4.w;
            if ((unsigned)d < N_NODES) {
                int pos = atomicAdd(&g_count[d], 1);
                if (pos < CAP)
                    g_esrc[(long long)d * CAP + pos] = ((unsigned)s < N_NODES) ? s : 0;
            }
        }
    }
}

// ---------------------------------------------------------------------------
// 2) fused aggregate + bf16-split tensor GEMM. 256 threads, 64 nodes/block.
//    Phase A2 gather: ONE WARP per node. Lane l loads index ep[base+l]
//    (one coalesced LDG per 32 edges), then shfl-broadcasts each index and
//    issues independent float2 feature loads -> MLP ~ deg (~12).
//    Phase B: 8 warps x (m16-tile, n32-half): 12 HMMA.m16n8k16 per k16 step.
// ---------------------------------------------------------------------------
#define NT 64
#define XSTR 66    // uint (bf16x2) row stride: 64 pairs + 2 pad

__global__ __launch_bounds__(256) void gemm_kernel(const float* __restrict__ h,
                                                   const float* __restrict__ b,
                                                   float* __restrict__ out) {
    __shared__ unsigned Xhi[NT * XSTR];   // 16,896 B
    __shared__ unsigned Xlo[NT * XSTR];   // 16,896 B

    int tid = threadIdx.x;
    int node0 = blockIdx.x * NT;
    int warp = tid >> 5;
    int lane = tid & 31;

    // --- Phase A1: self features -> pairs [0,32) ---
    for (int idx = tid; idx < NT * 16; idx += 256) {
        int n = idx >> 4, q = idx & 15;
        int node = node0 + n;
        float4 v = make_float4(0.f, 0.f, 0.f, 0.f);
        if (node < N_NODES) v = ((const float4*)(h + (long long)node * F))[q];
        unsigned h0, l0, h1, l1;
        split_pair(v.x, v.y, h0, l0);
        split_pair(v.z, v.w, h1, l1);
        ((uint2*)(Xhi + n * XSTR))[q] = make_uint2(h0, h1);
        ((uint2*)(Xlo + n * XSTR))[q] = make_uint2(l0, l1);
    }

    // --- Phase A2: neighbor mean, one warp per node, shfl-broadcast gather ---
    {
        const float2* h2 = (const float2*)h;   // node row = 32 float2
        for (int n = warp; n < NT; n += 8) {
            int node = node0 + n;
            float ax = 0.f, ay = 0.f;
            float inv = 0.f;
            if (node < N_NODES) {
                int deg = g_count[node];
                if (deg > CAP) deg = CAP;
                const int* ep = g_esrc + (long long)node * CAP;
                for (int base = 0; base < deg; base += 32) {
                    int myidx = 0;
                    if (base + lane < deg) myidx = ep[base + lane];   // 1 coalesced LDG
                    int m = deg - base;
                    if (m > 32) m = 32;
#pragma unroll 4
                    for (int e = 0; e < m; e++) {
                        int s = __shfl_sync(0xffffffffu, myidx, e);
                        float2 v = h2[(long long)s * 32 + lane];      // independent loads
                        ax += v.x;
                        ay += v.y;
                    }
                }
                inv = 1.f / fmaxf((float)deg, 1.f);
            }
            unsigned hi, lo;
            split_pair(ax * inv, ay * inv, hi, lo);
            Xhi[n * XSTR + 32 + lane] = hi;       // pairs [32,64)
            Xlo[n * XSTR + 32 + lane] = lo;
        }
    }
    __syncthreads();

    // --- tail: re-zero g_count for next replay (all reads done) ---
    for (int n = tid; n < NT; n += 256) {
        int node = node0 + n;
        if (node < N_NODES) g_count[node] = 0;
    }

    // --- Phase B: mma mainloop ---
    int g = lane >> 2;
    int t = lane & 3;
    int mt = warp & 3;          // m-tile: nodes [16*mt, 16*mt+16)
    int nh = warp >> 2;         // n-half: outs [32*nh, 32*nh+32)
    int n0 = mt * 16;

    float acc[4][4];
#pragma unroll
    for (int tl = 0; tl < 4; tl++)
#pragma unroll
        for (int r = 0; r < 4; r++) acc[tl][r] = 0.f;

#pragma unroll
    for (int ks = 0; ks < 8; ks++) {
        int pb = ks * 8;                          // pair-index base (k16 step)
        const unsigned* xh = Xhi + (n0 + g) * XSTR + pb;
        const unsigned* xl = Xlo + (n0 + g) * XSTR + pb;
        unsigned ahi[4], alo[4];
        ahi[0] = xh[t];                alo[0] = xl[t];
        ahi[1] = xh[8 * XSTR + t];     alo[1] = xl[8 * XSTR + t];
        ahi[2] = xh[t + 4];            alo[2] = xl[t + 4];
        ahi[3] = xh[8 * XSTR + t + 4]; alo[3] = xl[8 * XSTR + t + 4];
        const uint4* wp = g_wsplit + (ks * 8 + nh * 4) * 32 + lane;
#pragma unroll
        for (int tl = 0; tl < 4; tl++) {
            uint4 wv = __ldg(wp + tl * 32);       // {bh0, bh1, bl0, bl1}
            mma_bf16(acc[tl], ahi, wv.x, wv.y);   // hi*hi
            mma_bf16(acc[tl], ahi, wv.z, wv.w);   // hi*lo
            mma_bf16(acc[tl], alo, wv.x, wv.y);   // lo*hi
        }
    }

    // --- Epilogue ---
    int nodeA = node0 + n0 + g;
    int nodeB = nodeA + 8;
#pragma unroll
    for (int tl = 0; tl < 4; tl++) {
        int o0 = nh * 32 + tl * 8 + 2 * t;
        float bx = b[o0], by = b[o0 + 1];
        if (nodeA < N_NODES)
            *(float2*)(out + (long long)nodeA * F + o0) =
                make_float2(acc[tl][0] + bx, acc[tl][1] + by);
        if (nodeB < N_NODES)
            *(float2*)(out + (long long)nodeB * F + o0) =
                make_float2(acc[tl][2] + bx, acc[tl][3] + by);
    }
}

// ---------------------------------------------------------------------------
extern "C" void kernel_launch(void* const* d_in, const int* in_sizes, int n_in,
                              void* d_out, int out_size) {
    const float* h   = (const float*)d_in[0];
    const float* W   = (const float*)d_in[1];
    const float* b   = (const float*)d_in[2];
    const int*   src = (const int*)d_in[3];
    const int*   dst = (const int*)d_in[4];
    float* out = (float*)d_out;

    fill_kernel<<<FILL_BLOCKS + PREP_BLOCKS, 256>>>(src, dst, W);
    gemm_kernel<<<(N_NODES + NT - 1) / NT, 256>>>(h, b, out);
}

// round 16
// speedup vs baseline: 1.2894x; 1.2894x over previous
#include <cuda_runtime.h>
#include <cuda_bf16.h>
#include <cstdint>

#define N_NODES 100000
#define N_EDGES 1250000
#define F 64
#define K_DIM 128
#define CAP 64          // bucket capacity; P(deg > 64) ~ 1e-34 (guarded anyway)

// ---------------- device scratch ----------------
__device__ int g_count[N_NODES];              // in-degree (re-zeroed by gemm tail)
__device__ int g_esrc[(size_t)N_NODES * CAP]; // per-node src buckets (25.6 MB)

// W bf16-split fragments, mma m16n8k16 B layout:
// g_wsplit[(ks*8 + tl)*32 + lane] = {bh0, bh1, bl0, bl1} (each = bf16x2)
#define NFRAG (8 * 8 * 32)     // 2048
__device__ uint4 g_wsplit[NFRAG];

// split two fp32 into packed bf16x2 hi and lo (x = hi + lo, ~16 mantissa bits)
__device__ __forceinline__ void split_pair(float x0, float x1,
                                           unsigned& hi, unsigned& lo) {
    __nv_bfloat16 h0 = __float2bfloat16_rn(x0);
    __nv_bfloat16 h1 = __float2bfloat16_rn(x1);
    float r0 = x0 - __bfloat162float(h0);
    float r1 = x1 - __bfloat162float(h1);
    __nv_bfloat16 l0 = __float2bfloat16_rn(r0);
    __nv_bfloat16 l1 = __float2bfloat16_rn(r1);
    hi = (unsigned)__bfloat16_as_ushort(h0) | ((unsigned)__bfloat16_as_ushort(h1) << 16);
    lo = (unsigned)__bfloat16_as_ushort(l0) | ((unsigned)__bfloat16_as_ushort(l1) << 16);
}

__device__ __forceinline__ void mma_bf16(float d[4], const unsigned a[4],
                                         unsigned b0, unsigned b1) {
    asm volatile(
        "mma.sync.aligned.m16n8k16.row.col.f32.bf16.bf16.f32 "
        "{%0,%1,%2,%3}, {%4,%5,%6,%7}, {%8,%9}, {%0,%1,%2,%3};\n"
        : "+f"(d[0]), "+f"(d[1]), "+f"(d[2]), "+f"(d[3])
        : "r"(a[0]), "r"(a[1]), "r"(a[2]), "r"(a[3]), "r"(b0), "r"(b1));
}

// ---------------------------------------------------------------------------
// 1) single-pass bucket fill, 8 edges/thread (2 disjoint int4 quads) +
//    W fragment prep (last 8 blocks).
// ---------------------------------------------------------------------------
#define QUADS (N_EDGES / 4)                       // 312500 (even)
#define HALFQ (QUADS / 2)                         // 156250
#define FILL_BLOCKS ((HALFQ + 255) / 256)         // 611
#define PREP_BLOCKS ((NFRAG + 255) / 256)         // 8

__global__ __launch_bounds__(256) void fill_kernel(const int* __restrict__ src,
                                                   const int* __restrict__ dst,
                                                   const float* __restrict__ W) {
    if (blockIdx.x >= FILL_BLOCKS) {
        int idx = (blockIdx.x - FILL_BLOCKS) * 256 + threadIdx.x;
        if (idx < NFRAG) {
            int lane = idx & 31;
            int tl = (idx >> 5) & 7;
            int ks = idx >> 8;                 // 0..7, k-base = 16*ks
            int g = lane >> 2, t = lane & 3;
            int o = tl * 8 + g;
            const float* wr = W + o * K_DIM + ks * 16;
            unsigned bh0, bl0, bh1, bl1;
            split_pair(wr[2 * t],     wr[2 * t + 1], bh0, bl0);
            split_pair(wr[2 * t + 8], wr[2 * t + 9], bh1, bl1);
            g_wsplit[idx] = make_uint4(bh0, bh1, bl0, bl1);
        }
        return;
    }
    int i = blockIdx.x * blockDim.x + threadIdx.x;
    if (i >= HALFQ) return;                   // disjoint halves only
#pragma unroll
    for (int r = 0; r < 2; r++) {
        int ii = i + r * HALFQ;               // covers [0,QUADS) exactly once
        int4 s4 = ((const int4*)src)[ii];
        int4 d4 = ((const int4*)dst)[ii];
#pragma unroll
        for (int j = 0; j < 4; j++) {
            int d = (j == 0) ? d4.x : (j == 1) ? d4.y : (j == 2) ? d4.z : d4.w;
            int s = (j == 0) ? s4.x : (j == 1) ? s4.y : (j == 2) ? s4.z : s4.w;
            if ((unsigned)d < N_NODES) {
                int pos = atomicAdd(&g_count[d], 1);
                if (pos < CAP)
                    g_esrc[(long long)d * CAP + pos] = ((unsigned)s < N_NODES) ? s : 0;
            }
        }
    }
}

// ---------------------------------------------------------------------------
// 2) fused aggregate + bf16-split tensor GEMM. 256 threads, 64 nodes/block.
//    Phase A2: half-warp per node, int4 index loads, 8-deep float4 MLP.
//    Phase B: 8 warps x (m16-tile, n32-half): 12 HMMA.m16n8k16 per k16 step.
// ---------------------------------------------------------------------------
#define NT 64
#define XSTR 66    // uint (bf16x2) row stride: 64 pairs + 2 pad

__global__ __launch_bounds__(256) void gemm_kernel(const float* __restrict__ h,
                                                   const float* __restrict__ b,
                                                   float* __restrict__ out) {
    __shared__ unsigned Xhi[NT * XSTR];   // 16,896 B
    __shared__ unsigned Xlo[NT * XSTR];   // 16,896 B

    int tid = threadIdx.x;
    int node0 = blockIdx.x * NT;

    // --- Phase A1: self features -> pairs [0,32) ---
    for (int idx = tid; idx < NT * 16; idx += 256) {
        int n = idx >> 4, q = idx & 15;
        int node = node0 + n;
        float4 v = make_float4(0.f, 0.f, 0.f, 0.f);
        if (node < N_NODES) v = ((const float4*)(h + (long long)node * F))[q];
        unsigned h0, l0, h1, l1;
        split_pair(v.x, v.y, h0, l0);
        split_pair(v.z, v.w, h1, l1);
        ((uint2*)(Xhi + n * XSTR))[q] = make_uint2(h0, h1);
        ((uint2*)(Xlo + n * XSTR))[q] = make_uint2(l0, l1);
    }

    // --- Phase A2: neighbor mean, half-warp per node, 8-deep MLP ---
    {
        int hw = tid >> 4;        // 0..15 half-warps
        int ln = tid & 15;        // float4 slot within the 64-float row
        for (int n = hw; n < NT; n += 16) {
            int node = node0 + n;
            float4 a = make_float4(0.f, 0.f, 0.f, 0.f);
            float inv = 0.f;
            if (node < N_NODES) {
                int deg = g_count[node];
                if (deg > CAP) deg = CAP;               // overflow guard
                const int4* ep4 = (const int4*)(g_esrc + (long long)node * CAP);
                int e = 0;
                for (; e + 8 <= deg; e += 8) {
                    int4 i0 = ep4[e >> 2];
                    int4 i1 = ep4[(e >> 2) + 1];
                    float4 v0 = ((const float4*)(h + (long long)i0.x * F))[ln];
                    float4 v1 = ((const float4*)(h + (long long)i0.y * F))[ln];
                    float4 v2 = ((const float4*)(h + (long long)i0.z * F))[ln];
                    float4 v3 = ((const float4*)(h + (long long)i0.w * F))[ln];
                    float4 v4 = ((const float4*)(h + (long long)i1.x * F))[ln];
                    float4 v5 = ((const float4*)(h + (long long)i1.y * F))[ln];
                    float4 v6 = ((const float4*)(h + (long long)i1.z * F))[ln];
                    float4 v7 = ((const float4*)(h + (long long)i1.w * F))[ln];
                    a.x += (v0.x + v1.x) + (v2.x + v3.x) + (v4.x + v5.x) + (v6.x + v7.x);
                    a.y += (v0.y + v1.y) + (v2.y + v3.y) + (v4.y + v5.y) + (v6.y + v7.y);
                    a.z += (v0.z + v1.z) + (v2.z + v3.z) + (v4.z + v5.z) + (v6.z + v7.z);
                    a.w += (v0.w + v1.w) + (v2.w + v3.w) + (v4.w + v5.w) + (v6.w + v7.w);
                }
                for (; e + 4 <= deg; e += 4) {
                    int4 i0 = ep4[e >> 2];
                    float4 v0 = ((const float4*)(h + (long long)i0.x * F))[ln];
                    float4 v1 = ((const float4*)(h + (long long)i0.y * F))[ln];
                    float4 v2 = ((const float4*)(h + (long long)i0.z * F))[ln];
                    float4 v3 = ((const float4*)(h + (long long)i0.w * F))[ln];
                    a.x += (v0.x + v1.x) + (v2.x + v3.x);
                    a.y += (v0.y + v1.y) + (v2.y + v3.y);
                    a.z += (v0.z + v1.z) + (v2.z + v3.z);
                    a.w += (v0.w + v1.w) + (v2.w + v3.w);
                }
                for (; e < deg; e++) {
                    int s = ((const int*)ep4)[e];
                    float4 v = ((const float4*)(h + (long long)s * F))[ln];
                    a.x += v.x; a.y += v.y; a.z += v.z; a.w += v.w;
                }
                inv = 1.f / fmaxf((float)deg, 1.f);
            }
            unsigned h0, l0, h1, l1;
            split_pair(a.x * inv, a.y * inv, h0, l0);
            split_pair(a.z * inv, a.w * inv, h1, l1);
            ((uint2*)(Xhi + n * XSTR))[16 + ln] = make_uint2(h0, h1);
            ((uint2*)(Xlo + n * XSTR))[16 + ln] = make_uint2(l0, l1);
        }
    }
    __syncthreads();

    // --- tail: re-zero g_count for next replay (all reads done) ---
    for (int n = tid; n < NT; n += 256) {
        int node = node0 + n;
        if (node < N_NODES) g_count[node] = 0;
    }

    // --- Phase B: mma mainloop ---
    int warp = tid >> 5;
    int lane = tid & 31;
    int g = lane >> 2;
    int t = lane & 3;
    int mt = warp & 3;          // m-tile: nodes [16*mt, 16*mt+16)
    int nh = warp >> 2;         // n-half: outs [32*nh, 32*nh+32)
    int n0 = mt * 16;

    float acc[4][4];
#pragma unroll
    for (int tl = 0; tl < 4; tl++)
#pragma unroll
        for (int r = 0; r < 4; r++) acc[tl][r] = 0.f;

#pragma unroll
    for (int ks = 0; ks < 8; ks++) {
        int pb = ks * 8;                          // pair-index base (k16 step)
        const unsigned* xh = Xhi + (n0 + g) * XSTR + pb;
        const unsigned* xl = Xlo + (n0 + g) * XSTR + pb;
        unsigned ahi[4], alo[4];
        ahi[0] = xh[t];                alo[0] = xl[t];
        ahi[1] = xh[8 * XSTR + t];     alo[1] = xl[8 * XSTR + t];
        ahi[2] = xh[t + 4];            alo[2] = xl[t + 4];
        ahi[3] = xh[8 * XSTR + t + 4]; alo[3] = xl[8 * XSTR + t + 4];
        const uint4* wp = g_wsplit + (ks * 8 + nh * 4) * 32 + lane;
#pragma unroll
        for (int tl = 0; tl < 4; tl++) {
            uint4 wv = __ldg(wp + tl * 32);       // {bh0, bh1, bl0, bl1}
            mma_bf16(acc[tl], ahi, wv.x, wv.y);   // hi*hi
            mma_bf16(acc[tl], ahi, wv.z, wv.w);   // hi*lo
            mma_bf16(acc[tl], alo, wv.x, wv.y);   // lo*hi
        }
    }

    // --- Epilogue ---
    int nodeA = node0 + n0 + g;
    int nodeB = nodeA + 8;
#pragma unroll
    for (int tl = 0; tl < 4; tl++) {
        int o0 = nh * 32 + tl * 8 + 2 * t;
        float bx = b[o0], by = b[o0 + 1];
        if (nodeA < N_NODES)
            *(float2*)(out + (long long)nodeA * F + o0) =
                make_float2(acc[tl][0] + bx, acc[tl][1] + by);
        if (nodeB < N_NODES)
            *(float2*)(out + (long long)nodeB * F + o0) =
                make_float2(acc[tl][2] + bx, acc[tl][3] + by);
    }
}

// ---------------------------------------------------------------------------
extern "C" void kernel_launch(void* const* d_in, const int* in_sizes, int n_in,
                              void* d_out, int out_size) {
    const float* h   = (const float*)d_in[0];
    const float* W   = (const float*)d_in[1];
    const float* b   = (const float*)d_in[2];
    const int*   src = (const int*)d_in[3];
    const int*   dst = (const int*)d_in[4];
    float* out = (float*)d_out;

    fill_kernel<<<FILL_BLOCKS + PREP_BLOCKS, 256>>>(src, dst, W);
    gemm_kernel<<<(N_NODES + NT - 1) / NT, 256>>>(h, b, out);
}